// round 16
// baseline (speedup 1.0000x reference)
#include <cuda_runtime.h>
#include <cuda_fp16.h>
#include <cstdint>

// Problem constants
#define NN   64
#define DD   512
#define TT   256
#define QQ   6
#define CC   1024
#define NT   (NN*TT)              // 16384
#define OUT_QUANT   (NN*DD*TT)    // 8388608
#define OUT_IDX     (NT*QQ)       // 98304

// Scratch (device globals — no runtime allocation allowed)
__device__ __half g_res_h[(size_t)NT * DD];     // residual hi (fp16)
__device__ __half g_res_l[(size_t)NT * DD];     // residual lo (fp16)
__device__ __half g_cb_h[(size_t)QQ * CC * DD]; // codebook hi
__device__ float  g_cbnorm[QQ * CC];            // ||c||^2 per code per stage
__device__ float  g_rnorm2[NT];                 // ||residual_row||^2
__device__ int    g_cmax2[QQ];                  // max ||c||^2 per stage (float bits)
__device__ int    g_indices[NT * QQ];
__device__ int    g_hist2[QQ * CC];             // per-stage histograms
__device__ float  g_loss[QQ];

// ===========================================================================
// helpers
// ===========================================================================
__device__ __forceinline__ uint32_t smem_u32(const void* p) {
    uint32_t a;
    asm("{ .reg .u64 t; cvta.to.shared.u64 t, %1; cvt.u32.u64 %0, t; }" : "=r"(a) : "l"(p));
    return a;
}
__device__ __forceinline__ uint32_t swz(uint32_t off) {           // Swizzle<3,4,3>
    return off ^ ((off >> 3) & 0x70);
}
__device__ __forceinline__ unsigned int sortable_f32(float f) {
    unsigned int u = __float_as_uint(f);
    return (u & 0x80000000u) ? ~u : (u | 0x80000000u);
}

#define CP16(dst, src) \
    asm volatile("cp.async.ca.shared.global [%0], [%1], 16;" :: "r"(dst), "l"(src))
#define CP_COMMIT() asm volatile("cp.async.commit_group;" ::: "memory")
#define CP_WAIT0()  asm volatile("cp.async.wait_group 0;" ::: "memory")

__device__ __forceinline__ void ldsm_x4(uint32_t* r, uint32_t addr) {
    asm volatile("ldmatrix.sync.aligned.m8n8.x4.shared.b16 {%0,%1,%2,%3}, [%4];"
        : "=r"(r[0]), "=r"(r[1]), "=r"(r[2]), "=r"(r[3]) : "r"(addr));
}
__device__ __forceinline__ void mma_16816(float* d, const uint32_t* a,
                                          uint32_t b0, uint32_t b1) {
    asm volatile(
        "mma.sync.aligned.m16n8k16.row.col.f32.f16.f16.f32 "
        "{%0,%1,%2,%3}, {%4,%5,%6,%7}, {%8,%9}, {%0,%1,%2,%3};"
        : "+f"(d[0]), "+f"(d[1]), "+f"(d[2]), "+f"(d[3])
        : "r"(a[0]), "r"(a[1]), "r"(a[2]), "r"(a[3]), "r"(b0), "r"(b1));
}

// ===========================================================================
// init: zero hist2 + loss + rnorm2 + cmax (graph replays)
// ===========================================================================
__global__ void init_kernel() {
    int i = blockIdx.x * blockDim.x + threadIdx.x;   // grid 64 x 256 = 16384
    if (i < NT) g_rnorm2[i] = 0.0f;
    if (i < QQ * CC) g_hist2[i] = 0;
    if (i < QQ) { g_loss[i] = 0.0f; g_cmax2[i] = 0; }
}

// codebook prep: hi split, ||c||^2, per-stage max norm
__global__ void cbprep_kernel(const float* __restrict__ cb) {
    int code = blockIdx.x;             // 0..6143 (q*1024+c)
    int tid  = threadIdx.x;            // 128
    size_t base = (size_t)code * DD;
    float4 v = ((const float4*)(cb + base))[tid];

    __half2* hp = (__half2*)(g_cb_h + base + tid * 4);
    hp[0] = __halves2half2(__float2half(v.x), __float2half(v.y));
    hp[1] = __halves2half2(__float2half(v.z), __float2half(v.w));

    float s = v.x * v.x + v.y * v.y + v.z * v.z + v.w * v.w;
    #pragma unroll
    for (int off = 16; off > 0; off >>= 1) s += __shfl_down_sync(0xffffffffu, s, off);
    __shared__ float ws[4];
    if ((tid & 31) == 0) ws[tid >> 5] = s;
    __syncthreads();
    if (tid == 0) {
        float n = ws[0] + ws[1] + ws[2] + ws[3];
        g_cbnorm[code] = n;
        atomicMax(&g_cmax2[code >> 10], __float_as_int(n));  // norms > 0
    }
}

// transpose in: x (N, D, T) -> residual (NT, D) fp16 hi/lo; accumulate row norms
__global__ void transpose_in_kernel(const float* __restrict__ x) {
    __shared__ float tile[32][33];
    int n  = blockIdx.z;
    int t0 = blockIdx.x * 32;
    int d0 = blockIdx.y * 32;
    int tx = threadIdx.x, ty = threadIdx.y;  // (32, 8)

    #pragma unroll
    for (int i = 0; i < 4; i++) {
        int d = d0 + ty + i * 8;
        tile[ty + i * 8][tx] = x[(size_t)n * DD * TT + (size_t)d * TT + (t0 + tx)];
    }
    __syncthreads();
    #pragma unroll
    for (int i = 0; i < 4; i++) {
        int t = t0 + ty + i * 8;
        float v = tile[tx][ty + i * 8];
        size_t gi = (size_t)(n * TT + t) * DD + (d0 + tx);
        __half h = __float2half(v);
        g_res_h[gi] = h;
        g_res_l[gi] = __float2half(v - __half2float(h));
        float s = v * v;
        #pragma unroll
        for (int off = 16; off > 0; off >>= 1) s += __shfl_down_sync(0xffffffffu, s, off);
        if (tx == 0) atomicAdd(&g_rnorm2[n * TT + t], s);
    }
}

// ===========================================================================
// FUSED STAGE KERNEL: grid = 256 CTAs x 256 threads (8 warps).
// Each CTA: 64 rows vs ALL 1024 codes.
//   Phase 1 (MMA): 8 slices x 8 chunks, hh-only m16n8k16, warp tile 32x32
//     (2m x 4n warp grid). d_hh written straight to a 129KB smem region
//     (stride 2064B -> conflict-free for both scatter-write and linear read).
//   Phase 2 (refine): warp-synchronous, warp w owns rows w*8..w*8+8.
//     argmin + margin candidates from smem d_hh, exact fp32 dots for
//     candidates, residual update + loss + hist. No global distance array.
// ===========================================================================
#define MROWS   64
#define NCODES  128                 // per slice
#define NSLICE  (CC / NCODES)       // 8
#define KC      64
#define NCHUNK  (DD / KC)           // 8
#define NG      (NSLICE * NCHUNK)   // 64

#define OFF_AH   0
#define OFF_BH   (8*1024)
#define BUF_BYTES (24*1024)
#define OFF_D    (2*BUF_BYTES)      // 48 KB
#define DST      2064               // bytes per d row (516 words; %32 = 4)
#define ARG_SMEM (OFF_D + MROWS*DST)   // 49152 + 132096 = 181248

__global__ void __launch_bounds__(256) stage_kernel(const float* __restrict__ cb32, int q) {
    extern __shared__ char smem[];
    const uint32_t sb = smem_u32(smem);
    const int tid  = threadIdx.x;
    const int lane = tid & 31;
    const int wid  = tid >> 5;
    const int wm   = wid & 1;          // 0..1 (32 rows each)
    const int wn   = wid >> 1;         // 0..3 (32 codes each)
    const int rowBase = blockIdx.x * MROWS;

    const __half* __restrict__ resh = g_res_h;
    const __half* __restrict__ cbh  = g_cb_h + (size_t)q * CC * DD;
    const float*  __restrict__ norms = g_cbnorm + q * CC;

    float d[2][4][4];

    const int aRow  = (lane & 7) + ((lane >> 3) & 1) * 8;
    const int aK    = ((lane >> 4) & 1) * 8;
    const int bCode = (lane & 7) + ((lane >> 4) & 1) * 8;
    const int bK    = ((lane >> 3) & 1) * 8;

    auto issue = [&](int g) {
        const int ct = (g >> 3) * NCODES;
        const int k0 = (g & 7) * KC;
        const uint32_t bufb = sb + (g & 1) * BUF_BYTES;
        #pragma unroll
        for (int p = 0; p < 2; p++) {
            int seg = tid + p * 256;         // 0..511 (A: 64 rows x 8 segs)
            int row = seg >> 3, s8 = seg & 7;
            uint32_t so = swz((uint32_t)(row * 128 + s8 * 16));
            CP16(bufb + OFF_AH + so, resh + (size_t)(rowBase + row) * DD + k0 + s8 * 8);
        }
        #pragma unroll
        for (int p = 0; p < 4; p++) {
            int seg = tid + p * 256;         // 0..1023 (B: 128 codes x 8 segs)
            int row = seg >> 3, s8 = seg & 7;
            uint32_t so = swz((uint32_t)(row * 128 + s8 * 16));
            CP16(bufb + OFF_BH + so, cbh + (size_t)(ct + row) * DD + k0 + s8 * 8);
        }
        CP_COMMIT();
    };

    // ---------------- Phase 1: MMA over all slices ----------------
    issue(0);
    for (int g = 0; g < NG; g++) {
        CP_WAIT0();
        __syncthreads();

        if ((g & 7) == 0) {
            #pragma unroll
            for (int i = 0; i < 2; i++)
                #pragma unroll
                for (int j = 0; j < 4; j++)
                    #pragma unroll
                    for (int e = 0; e < 4; e++) d[i][j][e] = 0.0f;
        }

        if (g + 1 < NG) issue(g + 1);

        const uint32_t bufb = sb + (g & 1) * BUF_BYTES;
        #pragma unroll
        for (int kk = 0; kk < KC; kk += 16) {
            uint32_t ah[2][4];
            #pragma unroll
            for (int i = 0; i < 2; i++) {
                uint32_t so = swz((uint32_t)((wm * 32 + i * 16 + aRow) * 128 + (kk + aK) * 2));
                ldsm_x4(ah[i], bufb + OFF_AH + so);
            }
            #pragma unroll
            for (int j2 = 0; j2 < 2; j2++) {
                uint32_t bh[4];
                uint32_t so = swz((uint32_t)((wn * 32 + j2 * 16 + bCode) * 128 + (kk + bK) * 2));
                ldsm_x4(bh, bufb + OFF_BH + so);
                #pragma unroll
                for (int i = 0; i < 2; i++)
                    #pragma unroll
                    for (int h = 0; h < 2; h++)
                        mma_16816(d[i][j2 * 2 + h], ah[i], bh[h * 2], bh[h * 2 + 1]);
            }
        }

        // slice epilogue: write d_hh into smem d region (warp-private cells,
        // conflict-free by stride choice; no barrier needed)
        if ((g & 7) == 7) {
            const int ct = (g >> 3) * NCODES;
            char* dreg = smem + OFF_D;
            #pragma unroll
            for (int i = 0; i < 2; i++)
                #pragma unroll
                for (int j = 0; j < 4; j++)
                    #pragma unroll
                    for (int e2 = 0; e2 < 2; e2++) {
                        int rowL = wm * 32 + i * 16 + (lane >> 2) + e2 * 8;
                        int col  = ct + wn * 32 + j * 8 + 2 * (lane & 3);
                        float dx = __ldg(&norms[col])     - 2.0f * d[i][j][e2 * 2 + 0];
                        float dy = __ldg(&norms[col + 1]) - 2.0f * d[i][j][e2 * 2 + 1];
                        *(__half2*)(dreg + rowL * DST + col * 2) =
                            __halves2half2(__float2half(dx), __float2half(dy));
                    }
        }
    }
    __syncthreads();   // all d_hh visible to all warps

    // ---------------- Phase 2: warp-synchronous refine ----------------
    __shared__ float s_loss;
    if (tid == 0) s_loss = 0.0f;
    __syncthreads();

    const float cmax = sqrtf(__int_as_float(g_cmax2[q]));
    const char* dreg = smem + OFF_D;

    #pragma unroll 1
    for (int r8 = 0; r8 < 8; r8++) {
        const int rowL = wid * 8 + r8;
        const int row  = rowBase + rowL;

        // exact residual: a[2*j+e] <-> k = j*64 + lane*2 + e
        float a[16];
        const __half2* hr = (const __half2*)(g_res_h + (size_t)row * DD);
        const __half2* lr = (const __half2*)(g_res_l + (size_t)row * DD);
        #pragma unroll
        for (int j = 0; j < 8; j++) {
            __half2 h = hr[j * 32 + lane], l = lr[j * 32 + lane];
            a[2 * j]     = __low2float(h)  + __low2float(l);
            a[2 * j + 1] = __high2float(h) + __high2float(l);
        }

        // d_hh from smem (32 values per lane) + lane argmin (ascending c)
        const __half2* drow = (const __half2*)(dreg + rowL * DST);
        __half2 dh[16];
        float bv = 3.4e38f; int bi = 0;
        #pragma unroll
        for (int it = 0; it < 16; it++) {
            dh[it] = drow[it * 32 + lane];
            float dx = __low2float(dh[it]), dy = __high2float(dh[it]);
            int c0 = (it * 32 + lane) * 2;
            if (dx < bv) { bv = dx; bi = c0; }
            if (dy < bv) { bv = dy; bi = c0 + 1; }
        }
        unsigned long long key =
            ((unsigned long long)sortable_f32(bv) << 32) | (unsigned)bi;
        #pragma unroll
        for (int off = 16; off > 0; off >>= 1) {
            unsigned long long o = __shfl_xor_sync(0xffffffffu, key, off);
            if (o < key) key = o;
        }
        unsigned u = (unsigned)(key >> 32);
        float dmin = __uint_as_float((u & 0x80000000u) ? (u & 0x7FFFFFFFu) : ~u);

        // margin (pairwise fp16 dot bound + fp16 storage quantization)
        float eps = sqrtf(g_rnorm2[row]) * cmax * (1.0f / 128.0f) + 1.0f;
        float T = dmin + eps;

        // count candidates
        int ncand = 0;
        #pragma unroll
        for (int it = 0; it < 16; it++) {
            float dx = __low2float(dh[it]), dy = __high2float(dh[it]);
            ncand += __popc(__ballot_sync(0xffffffffu, dx <= T));
            ncand += __popc(__ballot_sync(0xffffffffu, dy <= T));
        }

        int bc;
        if (ncand == 1) {
            bc = (int)(unsigned)(key & 0xFFFFFFFFull);
        } else {
            float bd = 3.4e38f; bc = CC;
            #pragma unroll 4
            for (int it = 0; it < 16; it++) {
                float dx = __low2float(dh[it]), dy = __high2float(dh[it]);
                #pragma unroll
                for (int e = 0; e < 2; e++) {
                    unsigned mask = __ballot_sync(0xffffffffu, (e ? dy : dx) <= T);
                    while (mask) {
                        int src = __ffs(mask) - 1; mask &= mask - 1;
                        int c = (it * 32 + src) * 2 + e;
                        const float* crow = cb32 + (size_t)c * DD;
                        float p = 0.0f;
                        #pragma unroll
                        for (int j = 0; j < 8; j++) {
                            float2 cv = *(const float2*)(crow + j * 64 + lane * 2);
                            p += a[2 * j] * cv.x + a[2 * j + 1] * cv.y;
                        }
                        #pragma unroll
                        for (int off = 16; off > 0; off >>= 1)
                            p += __shfl_xor_sync(0xffffffffu, p, off);
                        float dd = norms[c] - 2.0f * p;
                        if (dd < bd || (dd == bd && c < bc)) { bd = dd; bc = c; }
                    }
                }
            }
        }

        if (lane == 0) {
            g_indices[row * QQ + q] = bc;
            atomicAdd(&g_hist2[q * CC + bc], 1);
        }

        // residual update + loss + forward row norm
        const float* crow = cb32 + (size_t)bc * DD;
        __half2* hw = (__half2*)(g_res_h + (size_t)row * DD);
        __half2* lw = (__half2*)(g_res_l + (size_t)row * DD);
        float lsum = 0.0f;
        #pragma unroll
        for (int j = 0; j < 8; j++) {
            float2 cv = *(const float2*)(crow + j * 64 + lane * 2);
            float r0 = a[2 * j] - cv.x;
            float r1 = a[2 * j + 1] - cv.y;
            __half h0 = __float2half(r0), h1 = __float2half(r1);
            hw[j * 32 + lane] = __halves2half2(h0, h1);
            lw[j * 32 + lane] = __halves2half2(__float2half(r0 - __half2float(h0)),
                                               __float2half(r1 - __half2float(h1)));
            lsum += r0 * r0 + r1 * r1;
        }
        #pragma unroll
        for (int off = 16; off > 0; off >>= 1)
            lsum += __shfl_xor_sync(0xffffffffu, lsum, off);
        if (lane == 0) {
            g_rnorm2[row] = lsum;
            atomicAdd(&s_loss, lsum);
        }
    }

    __syncthreads();
    if (tid == 0) atomicAdd(&g_loss[q], s_loss);
}

// ---------------------------------------------------------------------------
// output: quantized_out (N,D,T) = x - residual_final  (transpose back)
// ---------------------------------------------------------------------------
__global__ void transpose_out_kernel(const float* __restrict__ x, float* __restrict__ out) {
    __shared__ float tile[32][33];
    int n  = blockIdx.z;
    int t0 = blockIdx.x * 32;
    int d0 = blockIdx.y * 32;
    int tx = threadIdx.x, ty = threadIdx.y;  // (32, 8)

    #pragma unroll
    for (int i = 0; i < 4; i++) {
        int t = t0 + ty + i * 8;
        size_t gi = (size_t)(n * TT + t) * DD + (d0 + tx);
        tile[ty + i * 8][tx] = __half2float(g_res_h[gi]) + __half2float(g_res_l[gi]);
    }
    __syncthreads();
    #pragma unroll
    for (int i = 0; i < 4; i++) {
        int d = d0 + ty + i * 8;
        size_t gi = (size_t)n * DD * TT + (size_t)d * TT + (t0 + tx);
        out[gi] = x[gi] - tile[tx][ty + i * 8];
    }
}

__global__ void idx_kernel(float* __restrict__ out) {
    int i = blockIdx.x * blockDim.x + threadIdx.x;
    if (i < OUT_IDX) out[OUT_QUANT + i] = (float)g_indices[i];
}

// all 6 perplexities + mean loss
__global__ void finalize_kernel(float* __restrict__ out) {
    int tid = threadIdx.x;   // 256
    __shared__ float ws[8];
    __shared__ float perp_sum;
    if (tid == 0) perp_sum = 0.0f;
    __syncthreads();

    for (int q = 0; q < QQ; q++) {
        float s = 0.0f;
        for (int i = tid; i < CC; i += 256) {
            float p = (float)g_hist2[q * CC + i] * (1.0f / (float)NT);
            s += p * logf(p + 1e-10f);
        }
        #pragma unroll
        for (int off = 16; off > 0; off >>= 1) s += __shfl_down_sync(0xffffffffu, s, off);
        if ((tid & 31) == 0) ws[tid >> 5] = s;
        __syncthreads();
        if (tid == 0) {
            float t = 0.0f;
            #pragma unroll
            for (int i = 0; i < 8; i++) t += ws[i];
            perp_sum += expf(-t);
        }
        __syncthreads();
    }

    if (tid == 0) {
        float l = 0.0f;
        #pragma unroll
        for (int q = 0; q < QQ; q++) l += g_loss[q];
        out[OUT_QUANT + OUT_IDX + 0] = l / ((float)NT * (float)DD) / (float)QQ;
        out[OUT_QUANT + OUT_IDX + 1] = perp_sum / (float)QQ;
    }
}

// ---------------------------------------------------------------------------
extern "C" void kernel_launch(void* const* d_in, const int* in_sizes, int n_in,
                              void* d_out, int out_size) {
    const float* x  = (const float*)d_in[0];   // (64, 512, 256) fp32
    const float* cb = (const float*)d_in[1];   // (6, 1024, 512) fp32
    float* out = (float*)d_out;

    static bool attr_set = false;
    if (!attr_set) {
        cudaFuncSetAttribute(stage_kernel,
                             cudaFuncAttributeMaxDynamicSharedMemorySize, ARG_SMEM);
        attr_set = true;
    }

    init_kernel<<<64, 256>>>();

    dim3 tb(32, 8);
    dim3 tg(TT / 32, DD / 32, NN);   // (8, 16, 64)
    transpose_in_kernel<<<tg, tb>>>(x);

    cbprep_kernel<<<QQ * CC, 128>>>(cb);

    for (int q = 0; q < QQ; q++) {
        const float* cbq = cb + (size_t)q * CC * DD;
        stage_kernel<<<NT / MROWS, 256, ARG_SMEM>>>(cbq, q);   // 256 CTAs
    }

    transpose_out_kernel<<<tg, tb>>>(x, out);
    idx_kernel<<<(OUT_IDX + 255) / 256, 256>>>(out);
    finalize_kernel<<<1, 256>>>(out);
}

// round 17
// speedup vs baseline: 1.0880x; 1.0880x over previous
#include <cuda_runtime.h>
#include <cuda_fp16.h>
#include <cstdint>

// Problem constants
#define NN   64
#define DD   512
#define TT   256
#define QQ   6
#define CC   1024
#define NT   (NN*TT)              // 16384
#define OUT_QUANT   (NN*DD*TT)    // 8388608
#define OUT_IDX     (NT*QQ)       // 98304

// Scratch (device globals — no runtime allocation allowed)
__device__ __half g_res_h[(size_t)NT * DD];     // residual hi (fp16)
__device__ __half g_res_l[(size_t)NT * DD];     // residual lo (fp16)
__device__ __half g_cb_h[(size_t)QQ * CC * DD]; // codebook hi
__device__ float  g_cbnorm[QQ * CC];            // ||c||^2 per code per stage
__device__ float  g_rnorm2[NT];                 // ||residual_row||^2
__device__ int    g_cmax2[QQ];                  // max ||c||^2 per stage (float bits)
__device__ int    g_indices[NT * QQ];
__device__ int    g_hist2[QQ * CC];             // per-stage histograms
__device__ float  g_loss[QQ];

// ===========================================================================
// helpers
// ===========================================================================
__device__ __forceinline__ uint32_t smem_u32(const void* p) {
    uint32_t a;
    asm("{ .reg .u64 t; cvta.to.shared.u64 t, %1; cvt.u32.u64 %0, t; }" : "=r"(a) : "l"(p));
    return a;
}
__device__ __forceinline__ uint32_t swz(uint32_t off) {           // Swizzle<3,4,3>
    return off ^ ((off >> 3) & 0x70);
}
__device__ __forceinline__ unsigned int sortable_f32(float f) {
    unsigned int u = __float_as_uint(f);
    return (u & 0x80000000u) ? ~u : (u | 0x80000000u);
}
__device__ __forceinline__ float unsortable_f32(unsigned int u) {
    return __uint_as_float((u & 0x80000000u) ? (u & 0x7FFFFFFFu) : ~u);
}

#define CP16(dst, src) \
    asm volatile("cp.async.ca.shared.global [%0], [%1], 16;" :: "r"(dst), "l"(src))
#define CP_COMMIT() asm volatile("cp.async.commit_group;" ::: "memory")
#define CP_WAIT0()  asm volatile("cp.async.wait_group 0;" ::: "memory")

__device__ __forceinline__ void ldsm_x4(uint32_t* r, uint32_t addr) {
    asm volatile("ldmatrix.sync.aligned.m8n8.x4.shared.b16 {%0,%1,%2,%3}, [%4];"
        : "=r"(r[0]), "=r"(r[1]), "=r"(r[2]), "=r"(r[3]) : "r"(addr));
}
__device__ __forceinline__ void mma_16816(float* d, const uint32_t* a,
                                          uint32_t b0, uint32_t b1) {
    asm volatile(
        "mma.sync.aligned.m16n8k16.row.col.f32.f16.f16.f32 "
        "{%0,%1,%2,%3}, {%4,%5,%6,%7}, {%8,%9}, {%0,%1,%2,%3};"
        : "+f"(d[0]), "+f"(d[1]), "+f"(d[2]), "+f"(d[3])
        : "r"(a[0]), "r"(a[1]), "r"(a[2]), "r"(a[3]), "r"(b0), "r"(b1));
}

// ===========================================================================
// init: zero hist2 + loss + rnorm2 + cmax (graph replays)
// ===========================================================================
__global__ void init_kernel() {
    int i = blockIdx.x * blockDim.x + threadIdx.x;   // grid 64 x 256 = 16384
    if (i < NT) g_rnorm2[i] = 0.0f;
    if (i < QQ * CC) g_hist2[i] = 0;
    if (i < QQ) { g_loss[i] = 0.0f; g_cmax2[i] = 0; }
}

// codebook prep: hi split, ||c||^2, per-stage max norm
__global__ void cbprep_kernel(const float* __restrict__ cb) {
    int code = blockIdx.x;             // 0..6143 (q*1024+c)
    int tid  = threadIdx.x;            // 128
    size_t base = (size_t)code * DD;
    float4 v = ((const float4*)(cb + base))[tid];

    __half2* hp = (__half2*)(g_cb_h + base + tid * 4);
    hp[0] = __halves2half2(__float2half(v.x), __float2half(v.y));
    hp[1] = __halves2half2(__float2half(v.z), __float2half(v.w));

    float s = v.x * v.x + v.y * v.y + v.z * v.z + v.w * v.w;
    #pragma unroll
    for (int off = 16; off > 0; off >>= 1) s += __shfl_down_sync(0xffffffffu, s, off);
    __shared__ float ws[4];
    if ((tid & 31) == 0) ws[tid >> 5] = s;
    __syncthreads();
    if (tid == 0) {
        float n = ws[0] + ws[1] + ws[2] + ws[3];
        g_cbnorm[code] = n;
        atomicMax(&g_cmax2[code >> 10], __float_as_int(n));  // norms > 0
    }
}

// transpose in: x (N, D, T) -> residual (NT, D) fp16 hi/lo; accumulate row norms
__global__ void transpose_in_kernel(const float* __restrict__ x) {
    __shared__ float tile[32][33];
    int n  = blockIdx.z;
    int t0 = blockIdx.x * 32;
    int d0 = blockIdx.y * 32;
    int tx = threadIdx.x, ty = threadIdx.y;  // (32, 8)

    #pragma unroll
    for (int i = 0; i < 4; i++) {
        int d = d0 + ty + i * 8;
        tile[ty + i * 8][tx] = x[(size_t)n * DD * TT + (size_t)d * TT + (t0 + tx)];
    }
    __syncthreads();
    #pragma unroll
    for (int i = 0; i < 4; i++) {
        int t = t0 + ty + i * 8;
        float v = tile[tx][ty + i * 8];
        size_t gi = (size_t)(n * TT + t) * DD + (d0 + tx);
        __half h = __float2half(v);
        g_res_h[gi] = h;
        g_res_l[gi] = __float2half(v - __half2float(h));
        float s = v * v;
        #pragma unroll
        for (int off = 16; off > 0; off >>= 1) s += __shfl_down_sync(0xffffffffu, s, off);
        if (tx == 0) atomicAdd(&g_rnorm2[n * TT + t], s);
    }
}

// ===========================================================================
// FUSED STAGE KERNEL (no distance matrix): grid = 512 CTAs x 128 threads.
// CTA = 32 rows x ALL 1024 codes (8 slices of 128), K=512 in 8 chunks.
// 4 warps, warp tile 32 rows x 32 codes (2m-frag x 4n-frag), hh-only MMA.
// Per slice: distances in registers -> per-row packed atomicMin + candidate
// list append (superset: threshold uses running min >= final min).
// Tail: warp-synchronous refine (exact fp32 for candidates) + residual
// update + loss + hist. smem ~44KB -> 4 CTAs/SM, 512 CTAs = one wave.
// ===========================================================================
#define MR      32                  // rows per CTA
#define NCOD    128                 // codes per slice
#define NSL     (CC / NCOD)         // 8
#define KC      64
#define NCH     (DD / KC)           // 8
#define NGK     (NSL * NCH)         // 64
#define CAP     28

#define OFF_A   0
#define OFF_B   (4*1024)
#define BUFB    (20*1024)
#define STG_SMEM (2*BUFB)           // 40960 dynamic

__global__ void __launch_bounds__(128, 4) stage_kernel(const float* __restrict__ cb32, int q) {
    extern __shared__ char smem[];
    const uint32_t sb = smem_u32(smem);
    __shared__ unsigned long long s_min[MR];
    __shared__ float s_eps[MR];
    __shared__ int   s_cnt[MR];
    __shared__ int   s_list[MR][CAP];
    __shared__ float s_loss;

    const int tid  = threadIdx.x;
    const int lane = tid & 31;
    const int wid  = tid >> 5;          // 0..3 = code-column group
    const int rowBase = blockIdx.x * MR;

    const __half* __restrict__ resh = g_res_h;
    const __half* __restrict__ cbh  = g_cb_h + (size_t)q * CC * DD;
    const float*  __restrict__ norms = g_cbnorm + q * CC;

    if (tid < MR) {
        s_min[tid] = 0xFFFFFFFFFFFFFFFFull;
        s_cnt[tid] = 0;
        s_eps[tid] = sqrtf(g_rnorm2[rowBase + tid]) *
                     sqrtf(__int_as_float(g_cmax2[q])) * (1.0f / 128.0f) + 1e-3f;
    }
    if (tid == 0) s_loss = 0.0f;
    // (first use of s_min/s_eps is after several __syncthreads below)

    float d[2][4][4];

    const int aRow  = (lane & 7) + ((lane >> 3) & 1) * 8;
    const int aK    = ((lane >> 4) & 1) * 8;
    const int bCode = (lane & 7) + ((lane >> 4) & 1) * 8;
    const int bK    = ((lane >> 3) & 1) * 8;

    auto issue = [&](int g) {
        const int ct = (g >> 3) * NCOD;
        const int k0 = (g & 7) * KC;
        const uint32_t bufb = sb + (g & 1) * BUFB;
        #pragma unroll
        for (int p = 0; p < 2; p++) {
            int seg = tid + p * 128;         // 0..255 (A: 32 rows x 8 segs)
            int row = seg >> 3, s8 = seg & 7;
            uint32_t so = swz((uint32_t)(row * 128 + s8 * 16));
            CP16(bufb + OFF_A + so, resh + (size_t)(rowBase + row) * DD + k0 + s8 * 8);
        }
        #pragma unroll
        for (int p = 0; p < 8; p++) {
            int seg = tid + p * 128;         // 0..1023 (B: 128 codes x 8 segs)
            int row = seg >> 3, s8 = seg & 7;
            uint32_t so = swz((uint32_t)(row * 128 + s8 * 16));
            CP16(bufb + OFF_B + so, cbh + (size_t)(ct + row) * DD + k0 + s8 * 8);
        }
        CP_COMMIT();
    };

    // ---------------- Phase 1: MMA + streaming argmin ----------------
    issue(0);
    for (int g = 0; g < NGK; g++) {
        CP_WAIT0();
        __syncthreads();

        if ((g & 7) == 0) {
            #pragma unroll
            for (int i = 0; i < 2; i++)
                #pragma unroll
                for (int j = 0; j < 4; j++)
                    #pragma unroll
                    for (int e = 0; e < 4; e++) d[i][j][e] = 0.0f;
        }

        if (g + 1 < NGK) issue(g + 1);

        const uint32_t bufb = sb + (g & 1) * BUFB;
        #pragma unroll
        for (int kk = 0; kk < KC; kk += 16) {
            uint32_t ah[2][4];
            #pragma unroll
            for (int i = 0; i < 2; i++) {
                uint32_t so = swz((uint32_t)((i * 16 + aRow) * 128 + (kk + aK) * 2));
                ldsm_x4(ah[i], bufb + OFF_A + so);
            }
            #pragma unroll
            for (int j2 = 0; j2 < 2; j2++) {
                uint32_t bh[4];
                uint32_t so = swz((uint32_t)((wid * 32 + j2 * 16 + bCode) * 128 + (kk + bK) * 2));
                ldsm_x4(bh, bufb + OFF_B + so);
                #pragma unroll
                for (int i = 0; i < 2; i++)
                    #pragma unroll
                    for (int h = 0; h < 2; h++)
                        mma_16816(d[i][j2 * 2 + h], ah[i], bh[h * 2], bh[h * 2 + 1]);
            }
        }

        // ---- slice epilogue: fold registers into running min + lists ----
        if ((g & 7) == 7) {
            const int ct = (g >> 3) * NCOD;
            // pass 1: per-row packed (dist,code) min
            #pragma unroll
            for (int i = 0; i < 2; i++)
                #pragma unroll
                for (int e2 = 0; e2 < 2; e2++) {
                    int rowL = i * 16 + (lane >> 2) + e2 * 8;
                    unsigned long long k = 0xFFFFFFFFFFFFFFFFull;
                    #pragma unroll
                    for (int j = 0; j < 4; j++)
                        #pragma unroll
                        for (int e1 = 0; e1 < 2; e1++) {
                            int col = ct + wid * 32 + j * 8 + 2 * (lane & 3) + e1;
                            float dist = __ldg(&norms[col]) - 2.0f * d[i][j][e2 * 2 + e1];
                            unsigned long long kk2 =
                                ((unsigned long long)sortable_f32(dist) << 32) | (unsigned)col;
                            if (kk2 < k) k = kk2;
                        }
                    #pragma unroll
                    for (int off = 1; off < 4; off <<= 1) {
                        unsigned long long o = __shfl_xor_sync(0xffffffffu, k, off);
                        if (o < k) k = o;
                    }
                    if ((lane & 3) == 0) atomicMin(&s_min[rowL], k);
                }
            __syncthreads();   // min includes this whole slice
            // pass 2: append candidates (threshold >= final_min + eps -> superset)
            #pragma unroll
            for (int i = 0; i < 2; i++)
                #pragma unroll
                for (int e2 = 0; e2 < 2; e2++) {
                    int rowL = i * 16 + (lane >> 2) + e2 * 8;
                    float T = unsortable_f32((unsigned)(s_min[rowL] >> 32)) + s_eps[rowL];
                    #pragma unroll
                    for (int j = 0; j < 4; j++)
                        #pragma unroll
                        for (int e1 = 0; e1 < 2; e1++) {
                            int col = ct + wid * 32 + j * 8 + 2 * (lane & 3) + e1;
                            float dist = __ldg(&norms[col]) - 2.0f * d[i][j][e2 * 2 + e1];
                            if (dist <= T) {
                                int p = atomicAdd(&s_cnt[rowL], 1);
                                if (p < CAP) s_list[rowL][p] = col;
                            }
                        }
                }
            // next write to s_min is after the next chunk's __syncthreads
        }
    }
    __syncthreads();

    // ---------------- Phase 2: warp-synchronous refine + update ----------------
    #pragma unroll 1
    for (int r8 = 0; r8 < 8; r8++) {
        const int rowL = wid * 8 + r8;
        const int row  = rowBase + rowL;

        // exact residual: a[2*j+e] <-> k = j*64 + lane*2 + e
        float a[16];
        const __half2* hr = (const __half2*)(g_res_h + (size_t)row * DD);
        const __half2* lr = (const __half2*)(g_res_l + (size_t)row * DD);
        #pragma unroll
        for (int j = 0; j < 8; j++) {
            __half2 h = hr[j * 32 + lane], l = lr[j * 32 + lane];
            a[2 * j]     = __low2float(h)  + __low2float(l);
            a[2 * j + 1] = __high2float(h) + __high2float(l);
        }

        const int cnt = s_cnt[rowL];
        int bc;
        if (cnt <= 1) {
            bc = (int)(unsigned)(s_min[rowL] & 0xFFFFFFFFull);
        } else if (cnt <= CAP) {
            float bd = 3.4e38f; bc = CC;
            for (int ci = 0; ci < cnt; ci++) {
                int c = s_list[rowL][ci];
                const float* crow = cb32 + (size_t)c * DD;
                float p = 0.0f;
                #pragma unroll
                for (int j = 0; j < 8; j++) {
                    float2 cv = *(const float2*)(crow + j * 64 + lane * 2);
                    p += a[2 * j] * cv.x + a[2 * j + 1] * cv.y;
                }
                #pragma unroll
                for (int off = 16; off > 0; off >>= 1)
                    p += __shfl_xor_sync(0xffffffffu, p, off);
                float dd = norms[c] - 2.0f * p;
                if (dd < bd || (dd == bd && c < bc)) { bd = dd; bc = c; }
            }
        } else {
            // overflow fallback (provably-rare): exact scan of all codes
            float bd = 3.4e38f; bc = CC;
            for (int c = 0; c < CC; c++) {
                const float* crow = cb32 + (size_t)c * DD;
                float p = 0.0f;
                #pragma unroll
                for (int j = 0; j < 8; j++) {
                    float2 cv = *(const float2*)(crow + j * 64 + lane * 2);
                    p += a[2 * j] * cv.x + a[2 * j + 1] * cv.y;
                }
                #pragma unroll
                for (int off = 16; off > 0; off >>= 1)
                    p += __shfl_xor_sync(0xffffffffu, p, off);
                float dd = norms[c] - 2.0f * p;
                if (dd < bd || (dd == bd && c < bc)) { bd = dd; bc = c; }
            }
        }

        if (lane == 0) {
            g_indices[row * QQ + q] = bc;
            atomicAdd(&g_hist2[q * CC + bc], 1);
        }

        // residual update + loss + forward row norm
        const float* crow = cb32 + (size_t)bc * DD;
        __half2* hw = (__half2*)(g_res_h + (size_t)row * DD);
        __half2* lw = (__half2*)(g_res_l + (size_t)row * DD);
        float lsum = 0.0f;
        #pragma unroll
        for (int j = 0; j < 8; j++) {
            float2 cv = *(const float2*)(crow + j * 64 + lane * 2);
            float r0 = a[2 * j] - cv.x;
            float r1 = a[2 * j + 1] - cv.y;
            __half h0 = __float2half(r0), h1 = __float2half(r1);
            hw[j * 32 + lane] = __halves2half2(h0, h1);
            lw[j * 32 + lane] = __halves2half2(__float2half(r0 - __half2float(h0)),
                                               __float2half(r1 - __half2float(h1)));
            lsum += r0 * r0 + r1 * r1;
        }
        #pragma unroll
        for (int off = 16; off > 0; off >>= 1)
            lsum += __shfl_xor_sync(0xffffffffu, lsum, off);
        if (lane == 0) {
            g_rnorm2[row] = lsum;
            atomicAdd(&s_loss, lsum);
        }
    }

    __syncthreads();
    if (tid == 0) atomicAdd(&g_loss[q], s_loss);
}

// ---------------------------------------------------------------------------
// output: quantized_out (N,D,T) = x - residual_final  (transpose back)
// ---------------------------------------------------------------------------
__global__ void transpose_out_kernel(const float* __restrict__ x, float* __restrict__ out) {
    __shared__ float tile[32][33];
    int n  = blockIdx.z;
    int t0 = blockIdx.x * 32;
    int d0 = blockIdx.y * 32;
    int tx = threadIdx.x, ty = threadIdx.y;  // (32, 8)

    #pragma unroll
    for (int i = 0; i < 4; i++) {
        int t = t0 + ty + i * 8;
        size_t gi = (size_t)(n * TT + t) * DD + (d0 + tx);
        tile[ty + i * 8][tx] = __half2float(g_res_h[gi]) + __half2float(g_res_l[gi]);
    }
    __syncthreads();
    #pragma unroll
    for (int i = 0; i < 4; i++) {
        int d = d0 + ty + i * 8;
        size_t gi = (size_t)n * DD * TT + (size_t)d * TT + (t0 + tx);
        out[gi] = x[gi] - tile[tx][ty + i * 8];
    }
}

__global__ void idx_kernel(float* __restrict__ out) {
    int i = blockIdx.x * blockDim.x + threadIdx.x;
    if (i < OUT_IDX) out[OUT_QUANT + i] = (float)g_indices[i];
}

// all 6 perplexities + mean loss
__global__ void finalize_kernel(float* __restrict__ out) {
    int tid = threadIdx.x;   // 256
    __shared__ float ws[8];
    __shared__ float perp_sum;
    if (tid == 0) perp_sum = 0.0f;
    __syncthreads();

    for (int q = 0; q < QQ; q++) {
        float s = 0.0f;
        for (int i = tid; i < CC; i += 256) {
            float p = (float)g_hist2[q * CC + i] * (1.0f / (float)NT);
            s += p * logf(p + 1e-10f);
        }
        #pragma unroll
        for (int off = 16; off > 0; off >>= 1) s += __shfl_down_sync(0xffffffffu, s, off);
        if ((tid & 31) == 0) ws[tid >> 5] = s;
        __syncthreads();
        if (tid == 0) {
            float t = 0.0f;
            #pragma unroll
            for (int i = 0; i < 8; i++) t += ws[i];
            perp_sum += expf(-t);
        }
        __syncthreads();
    }

    if (tid == 0) {
        float l = 0.0f;
        #pragma unroll
        for (int q = 0; q < QQ; q++) l += g_loss[q];
        out[OUT_QUANT + OUT_IDX + 0] = l / ((float)NT * (float)DD) / (float)QQ;
        out[OUT_QUANT + OUT_IDX + 1] = perp_sum / (float)QQ;
    }
}

// ---------------------------------------------------------------------------
extern "C" void kernel_launch(void* const* d_in, const int* in_sizes, int n_in,
                              void* d_out, int out_size) {
    const float* x  = (const float*)d_in[0];   // (64, 512, 256) fp32
    const float* cb = (const float*)d_in[1];   // (6, 1024, 512) fp32
    float* out = (float*)d_out;

    init_kernel<<<64, 256>>>();

    dim3 tb(32, 8);
    dim3 tg(TT / 32, DD / 32, NN);   // (8, 16, 64)
    transpose_in_kernel<<<tg, tb>>>(x);

    cbprep_kernel<<<QQ * CC, 128>>>(cb);

    for (int q = 0; q < QQ; q++) {
        const float* cbq = cb + (size_t)q * CC * DD;
        stage_kernel<<<NT / MR, 128, STG_SMEM>>>(cbq, q);   // 512 CTAs
    }

    transpose_out_kernel<<<tg, tb>>>(x, out);
    idx_kernel<<<(OUT_IDX + 255) / 256, 256>>>(out);
    finalize_kernel<<<1, 256>>>(out);
}